// round 6
// baseline (speedup 1.0000x reference)
#include <cuda_runtime.h>
#include <math.h>
#include <math_constants.h>

// Problem constants (fixed by setup_inputs)
#define D0   64
#define HH   2
#define CC   64
#define FF   128
#define NMAX 80000
#define EMAX 1280000

// ---------------- scratch ----------------
__device__ float g_h   [(size_t)NMAX * FF];
__device__ float g_x1  [(size_t)NMAX * FF];
__device__ float g_out1[(size_t)NMAX * CC];
__device__ float g_asrc[NMAX * HH];
__device__ float g_adst[NMAX * HH];
__device__ int   g_cnt   [NMAX];
__device__ int   g_start [NMAX];
__device__ int   g_cursor[NMAX];
__device__ int   g_need  [NMAX];
__device__ int   g_csrsrc[EMAX];

__device__ __forceinline__ float lrelu(float x) {
    return x >= 0.0f ? x : 0.2f * x;
}

// ---------------- GEMM: Y[n, FF] = X[n, K] @ W[K, FF] ----------------
template<int K>
__global__ void gemm_rowpanel(const float* __restrict__ A,
                              const float* __restrict__ B,
                              int split,
                              const float* __restrict__ W,
                              float* __restrict__ Y,
                              int n) {
    const int RPB = 16;
    __shared__ float xs[RPB][K];
    int r0 = blockIdx.x * RPB;
    int t  = threadIdx.x;          // 0..255
    int col  = t & 127;
    int half = t >> 7;

    for (int idx = t; idx < RPB * K; idx += 256) {
        int r = idx / K, k = idx % K;
        int gr = r0 + r;
        float v = 0.0f;
        if (gr < n) {
            const float* src = (gr < split) ? (A + (size_t)gr * K)
                                            : (B + (size_t)(gr - split) * K);
            v = src[k];
        }
        xs[r][k] = v;
    }
    __syncthreads();

    float acc[8];
#pragma unroll
    for (int r = 0; r < 8; ++r) acc[r] = 0.0f;
    int rbase = half * 8;

    for (int k = 0; k < K; ++k) {
        float w = W[k * FF + col];
#pragma unroll
        for (int r = 0; r < 8; ++r) acc[r] += xs[rbase + r][k] * w;
    }

#pragma unroll
    for (int r = 0; r < 8; ++r) {
        int gr = r0 + rbase + r;
        if (gr < n) Y[(size_t)gr * FF + col] = acc[r];
    }
}

// ---------------- per-node attention scalars ----------------
__global__ void attn_scores(const float* __restrict__ h,
                            const float* __restrict__ att_src,
                            const float* __restrict__ att_dst,
                            int n) {
    int gw   = (blockIdx.x * blockDim.x + threadIdx.x) >> 5;
    int lane = threadIdx.x & 31;
    if (gw >= n * HH) return;
    int node = gw / HH, head = gw % HH;
    const float* hr = h + (size_t)node * FF + head * CC;

    float s = 0.0f, d = 0.0f;
#pragma unroll
    for (int c = lane; c < CC; c += 32) {
        float v = hr[c];
        s += v * att_src[head * CC + c];
        d += v * att_dst[head * CC + c];
    }
#pragma unroll
    for (int o = 16; o > 0; o >>= 1) {
        s += __shfl_down_sync(0xffffffffu, s, o);
        d += __shfl_down_sync(0xffffffffu, d, o);
    }
    if (lane == 0) { g_asrc[gw] = s; g_adst[gw] = d; }
}

// ---------------- CSR build ----------------
__global__ void zero_cnt_need(int n) {
    int i = blockIdx.x * blockDim.x + threadIdx.x;
    if (i < n) { g_cnt[i] = 0; g_need[i] = 0; }
}

__global__ void hist_dst(const int* __restrict__ dst, int E) {
    int e = blockIdx.x * blockDim.x + threadIdx.x;
    if (e < E) atomicAdd(&g_cnt[dst[e]], 1);
}

__global__ void mark_needed(const int* __restrict__ uidx,
                            const int* __restrict__ iidx,
                            int nu, int B) {
    int i = blockIdx.x * blockDim.x + threadIdx.x;
    if (i < B)          g_need[uidx[i]] = 1;
    else if (i < 2 * B) g_need[nu + iidx[i - B]] = 1;
}

// single-block full exclusive scan of g_cnt -> g_start, g_cursor
__global__ void scan_all(int n) {
    __shared__ int sm[1024];
    int t = threadIdx.x;
    int chunk = (n + 1023) / 1024;
    int b0 = t * chunk;
    int e0 = min(b0 + chunk, n);

    int sum = 0;
    for (int i = b0; i < e0; ++i) sum += g_cnt[i];
    sm[t] = sum;
    __syncthreads();
    for (int off = 1; off < 1024; off <<= 1) {
        int v = (t >= off) ? sm[t - off] : 0;
        __syncthreads();
        sm[t] += v;
        __syncthreads();
    }
    int run = sm[t] - sum;   // exclusive prefix of this thread's chunk
    for (int i = b0; i < e0; ++i) {
        int c = g_cnt[i];
        g_start[i]  = run;
        g_cursor[i] = run;
        run += c;
    }
}

__global__ void scatter_edges(const int* __restrict__ src,
                              const int* __restrict__ dst, int E) {
    int e = blockIdx.x * blockDim.x + threadIdx.x;
    if (e >= E) return;
    int pos = atomicAdd(&g_cursor[dst[e]], 1);
    g_csrsrc[pos] = src[e];
}

// ---------------- layer-0 aggregation (concat heads), CSR gather ----------------
// warp per dst node; lane l handles float4 cols [4l,4l+4); heads split at lane 16
__global__ void agg_concat_csr(const float* __restrict__ h,
                               const float* __restrict__ bias,
                               float* __restrict__ out, int n) {
    int d    = (blockIdx.x * blockDim.x + threadIdx.x) >> 5;
    int lane = threadIdx.x & 31;
    if (d >= n) return;
    int hsel = lane >> 4;

    float2 adp = ((const float2*)g_adst)[d];
    int start = g_start[d];
    int deg   = g_cnt[d];

    float4 acc = make_float4(0.f, 0.f, 0.f, 0.f);
    float  den = 0.f;

    int sj_next = 0;
    if (lane < deg) sj_next = g_csrsrc[start + lane];

    for (int base = 0; base < deg; base += 32) {
        int m = min(32, deg - base);
        int sj = sj_next;
        int nb = base + 32;
        if (nb + lane < deg) sj_next = g_csrsrc[start + nb + lane];

        float w0 = 0.f, w1 = 0.f;
        if (lane < m) {
            float2 as = ((const float2*)g_asrc)[sj];
            w0 = __expf(lrelu(as.x + adp.x));
            w1 = __expf(lrelu(as.y + adp.y));
        }
        for (int k = 0; k < m; ++k) {
            int   s  = __shfl_sync(0xffffffffu, sj, k);
            float wa = __shfl_sync(0xffffffffu, w0, k);
            float wb = __shfl_sync(0xffffffffu, w1, k);
            float w  = (hsel == 0) ? wa : wb;
            float4 v = ((const float4*)(h + (size_t)s * FF))[lane];
            acc.x += w * v.x; acc.y += w * v.y;
            acc.z += w * v.z; acc.w += w * v.w;
            den += w;
        }
    }
    float inv = 1.0f / (den + 1e-16f);
    float4 b  = ((const float4*)bias)[lane];
    float4 o  = make_float4(acc.x * inv + b.x, acc.y * inv + b.y,
                            acc.z * inv + b.z, acc.w * inv + b.w);
    ((float4*)(out + (size_t)d * FF))[lane] = o;
}

// ---------------- layer-1 aggregation (mean over heads), needed dsts only ----
// warp per dst node; lane l handles cols {2l, 2l+1} of both heads
__global__ void agg_mean_csr(const float* __restrict__ h,
                             const float* __restrict__ bias,
                             float* __restrict__ out, int n) {
    int d    = (blockIdx.x * blockDim.x + threadIdx.x) >> 5;
    int lane = threadIdx.x & 31;
    if (d >= n) return;
    if (!g_need[d]) return;        // dead dst: scorer never reads it

    float2 adp = ((const float2*)g_adst)[d];
    int start = g_start[d];
    int deg   = g_cnt[d];
    int c = lane * 2;

    float2 acc0 = make_float2(0.f, 0.f), acc1 = make_float2(0.f, 0.f);
    float den0 = 0.f, den1 = 0.f;

    int sj_next = 0;
    if (lane < deg) sj_next = g_csrsrc[start + lane];

    for (int base = 0; base < deg; base += 32) {
        int m = min(32, deg - base);
        int sj = sj_next;
        int nb = base + 32;
        if (nb + lane < deg) sj_next = g_csrsrc[start + nb + lane];

        float w0 = 0.f, w1 = 0.f;
        if (lane < m) {
            float2 as = ((const float2*)g_asrc)[sj];
            w0 = __expf(lrelu(as.x + adp.x));
            w1 = __expf(lrelu(as.y + adp.y));
        }
        for (int k = 0; k < m; ++k) {
            int   s  = __shfl_sync(0xffffffffu, sj, k);
            float wa = __shfl_sync(0xffffffffu, w0, k);
            float wb = __shfl_sync(0xffffffffu, w1, k);
            const float* hr = h + (size_t)s * FF;
            float2 v0 = *(const float2*)(hr + c);
            float2 v1 = *(const float2*)(hr + CC + c);
            acc0.x += wa * v0.x; acc0.y += wa * v0.y;
            acc1.x += wb * v1.x; acc1.y += wb * v1.y;
            den0 += wa; den1 += wb;
        }
    }
    float i0 = 1.0f / (den0 + 1e-16f);
    float i1 = 1.0f / (den1 + 1e-16f);
    float2 b = ((const float2*)bias)[lane];
    float2 o = make_float2(0.5f * (acc0.x * i0 + acc1.x * i1) + b.x,
                           0.5f * (acc0.y * i0 + acc1.y * i1) + b.y);
    *(float2*)(out + (size_t)d * CC + c) = o;
}

// ---------------- final scorer ----------------
__global__ void score_pairs(const float* __restrict__ emb,
                            const int* __restrict__ uidx,
                            const int* __restrict__ iidx,
                            int nu, float* __restrict__ out, int B) {
    int warp = (blockIdx.x * blockDim.x + threadIdx.x) >> 5;
    int lane = threadIdx.x & 31;
    if (warp >= B) return;
    const float* gu = emb + (size_t)uidx[warp] * CC;
    const float* gi = emb + (size_t)(nu + iidx[warp]) * CC;
    float s = gu[lane] * gi[lane] + gu[lane + 32] * gi[lane + 32];
#pragma unroll
    for (int o = 16; o > 0; o >>= 1) s += __shfl_down_sync(0xffffffffu, s, o);
    if (lane == 0) out[warp] = s;
}

// ---------------- launch ----------------
extern "C" void kernel_launch(void* const* d_in, const int* in_sizes, int n_in,
                              void* d_out, int out_size) {
    const float* Gu  = (const float*)d_in[0];
    const float* Gi  = (const float*)d_in[1];
    const float* W0  = (const float*)d_in[2];
    const float* as0 = (const float*)d_in[3];
    const float* ad0 = (const float*)d_in[4];
    const float* b0  = (const float*)d_in[5];
    const float* W1  = (const float*)d_in[6];
    const float* as1 = (const float*)d_in[7];
    const float* ad1 = (const float*)d_in[8];
    const float* b1  = (const float*)d_in[9];
    const int*   ei  = (const int*)d_in[10];
    const int*   uix = (const int*)d_in[11];
    const int*   iix = (const int*)d_in[12];
    float* out = (float*)d_out;

    const int NU = in_sizes[0] / D0;
    const int NI = in_sizes[1] / D0;
    const int N  = NU + NI;
    const int E  = in_sizes[10] / 2;
    const int B  = in_sizes[11];
    const int* src = ei;
    const int* dst = ei + E;

    float *ph, *px1, *pout1;
    cudaGetSymbolAddress((void**)&ph,    g_h);
    cudaGetSymbolAddress((void**)&px1,   g_x1);
    cudaGetSymbolAddress((void**)&pout1, g_out1);

    const int TB = 256;
    int gemm_blocks  = (N + 15) / 16;
    int attn_grid    = (N * HH * 32 + TB - 1) / TB;
    int edge_grid    = (E + TB - 1) / TB;
    int node_grid    = (N + TB - 1) / TB;
    int warpnode_grid= (N * 32 + TB - 1) / TB;

    // ---------- CSR build (shared by both layers) ----------
    zero_cnt_need<<<node_grid, TB>>>(N);
    hist_dst<<<edge_grid, TB>>>(dst, E);
    mark_needed<<<(2 * B + TB - 1) / TB, TB>>>(uix, iix, NU, B);
    scan_all<<<1, 1024>>>(N);
    scatter_edges<<<edge_grid, TB>>>(src, dst, E);

    // ---------- layer 0 ----------
    gemm_rowpanel<D0><<<gemm_blocks, 256>>>(Gu, Gi, NU, W0, ph, N);
    attn_scores<<<attn_grid, TB>>>(ph, as0, ad0, N);
    agg_concat_csr<<<warpnode_grid, TB>>>(ph, b0, px1, N);

    // ---------- layer 1 ----------
    gemm_rowpanel<FF><<<gemm_blocks, 256>>>(px1, px1, N, W1, ph, N);
    attn_scores<<<attn_grid, TB>>>(ph, as1, ad1, N);
    agg_mean_csr<<<warpnode_grid, TB>>>(ph, b1, pout1, N);

    // ---------- scorer ----------
    score_pairs<<<(B * 32 + TB - 1) / TB, TB>>>(pout1, uix, iix, NU, out, B);
}

// round 8
// speedup vs baseline: 1.3472x; 1.3472x over previous
#include <cuda_runtime.h>
#include <math.h>
#include <math_constants.h>

// Problem constants (fixed by setup_inputs)
#define D0   64
#define HH   2
#define CC   64
#define FF   128
#define NMAX 80000
#define EMAX 1280000
#define SCAN_BLK 1024

// ---------------- scratch ----------------
__device__ float g_h   [(size_t)NMAX * FF];
__device__ float g_x1  [(size_t)NMAX * FF];
__device__ float g_out1[(size_t)NMAX * CC];
__device__ float g_asrc[NMAX * HH];
__device__ float g_adst[NMAX * HH];
__device__ int   g_cnt   [NMAX];
__device__ int   g_start [NMAX];
__device__ int   g_cursor[NMAX];
__device__ int   g_need  [NMAX];
__device__ int   g_part  [256];
__device__ int   g_csrsrc[EMAX];

__device__ __forceinline__ float lrelu(float x) {
    return x >= 0.0f ? x : 0.2f * x;
}

// ---------------- GEMM: Y[n, FF] = X[n, K] @ W[K, FF] ----------------
template<int K>
__global__ void gemm_rowpanel(const float* __restrict__ A,
                              const float* __restrict__ B,
                              int split,
                              const float* __restrict__ W,
                              float* __restrict__ Y,
                              int n) {
    const int RPB = 16;
    __shared__ float xs[RPB][K];
    int r0 = blockIdx.x * RPB;
    int t  = threadIdx.x;          // 0..255
    int col  = t & 127;
    int half = t >> 7;

    for (int idx = t; idx < RPB * K; idx += 256) {
        int r = idx / K, k = idx % K;
        int gr = r0 + r;
        float v = 0.0f;
        if (gr < n) {
            const float* src = (gr < split) ? (A + (size_t)gr * K)
                                            : (B + (size_t)(gr - split) * K);
            v = src[k];
        }
        xs[r][k] = v;
    }
    __syncthreads();

    float acc[8];
#pragma unroll
    for (int r = 0; r < 8; ++r) acc[r] = 0.0f;
    int rbase = half * 8;

    for (int k = 0; k < K; ++k) {
        float w = W[k * FF + col];
#pragma unroll
        for (int r = 0; r < 8; ++r) acc[r] += xs[rbase + r][k] * w;
    }

#pragma unroll
    for (int r = 0; r < 8; ++r) {
        int gr = r0 + rbase + r;
        if (gr < n) Y[(size_t)gr * FF + col] = acc[r];
    }
}

// ---------------- per-node attention scalars ----------------
__global__ void attn_scores(const float* __restrict__ h,
                            const float* __restrict__ att_src,
                            const float* __restrict__ att_dst,
                            int n) {
    int gw   = (blockIdx.x * blockDim.x + threadIdx.x) >> 5;
    int lane = threadIdx.x & 31;
    if (gw >= n * HH) return;
    int node = gw / HH, head = gw % HH;
    const float* hr = h + (size_t)node * FF + head * CC;

    float s = 0.0f, d = 0.0f;
#pragma unroll
    for (int c = lane; c < CC; c += 32) {
        float v = hr[c];
        s += v * att_src[head * CC + c];
        d += v * att_dst[head * CC + c];
    }
#pragma unroll
    for (int o = 16; o > 0; o >>= 1) {
        s += __shfl_down_sync(0xffffffffu, s, o);
        d += __shfl_down_sync(0xffffffffu, d, o);
    }
    if (lane == 0) { g_asrc[gw] = s; g_adst[gw] = d; }
}

// ---------------- CSR build ----------------
__global__ void zero_cnt_need(int n) {
    int i = blockIdx.x * blockDim.x + threadIdx.x;
    if (i < n) { g_cnt[i] = 0; g_need[i] = 0; }
}

__global__ void hist_dst(const int* __restrict__ dst, int E) {
    int e = blockIdx.x * blockDim.x + threadIdx.x;
    if (e < E) atomicAdd(&g_cnt[dst[e]], 1);
}

__global__ void mark_needed(const int* __restrict__ uidx,
                            const int* __restrict__ iidx,
                            int nu, int B) {
    int i = blockIdx.x * blockDim.x + threadIdx.x;
    if (i < B)          g_need[uidx[i]] = 1;
    else if (i < 2 * B) g_need[nu + iidx[i - B]] = 1;
}

__global__ void scan1(int n) {
    __shared__ int sm[SCAN_BLK];
    int i = blockIdx.x * SCAN_BLK + threadIdx.x;
    int v = (i < n) ? g_cnt[i] : 0;
    sm[threadIdx.x] = v;
    __syncthreads();
    for (int off = 1; off < SCAN_BLK; off <<= 1) {
        int t = (threadIdx.x >= off) ? sm[threadIdx.x - off] : 0;
        __syncthreads();
        sm[threadIdx.x] += t;
        __syncthreads();
    }
    if (i < n) g_start[i] = sm[threadIdx.x] - v;   // exclusive
    if (threadIdx.x == SCAN_BLK - 1) g_part[blockIdx.x] = sm[SCAN_BLK - 1];
}

__global__ void scan2(int nblocks) {
    __shared__ int sm[256];
    int t = threadIdx.x;
    int v = (t < nblocks) ? g_part[t] : 0;
    sm[t] = v;
    __syncthreads();
    for (int off = 1; off < 256; off <<= 1) {
        int u = (t >= off) ? sm[t - off] : 0;
        __syncthreads();
        sm[t] += u;
        __syncthreads();
    }
    if (t < nblocks) g_part[t] = sm[t] - v;        // exclusive
}

__global__ void scan3(int n) {
    int i = blockIdx.x * SCAN_BLK + threadIdx.x;
    if (i >= n) return;
    int s = g_start[i] + g_part[blockIdx.x];
    g_start[i]  = s;
    g_cursor[i] = s;
}

__global__ void scatter_edges(const int* __restrict__ src,
                              const int* __restrict__ dst, int E) {
    int e = blockIdx.x * blockDim.x + threadIdx.x;
    if (e >= E) return;
    int pos = atomicAdd(&g_cursor[dst[e]], 1);
    g_csrsrc[pos] = src[e];
}

// ---------------- layer-0 aggregation (concat heads), CSR gather ----------------
// warp per dst node; lane l handles float4 cols [4l,4l+4); heads split at lane 16
__global__ void agg_concat_csr(const float* __restrict__ h,
                               const float* __restrict__ bias,
                               float* __restrict__ out, int n) {
    int d    = (blockIdx.x * blockDim.x + threadIdx.x) >> 5;
    int lane = threadIdx.x & 31;
    if (d >= n) return;
    int hsel = lane >> 4;

    float2 adp = ((const float2*)g_adst)[d];
    int start = g_start[d];
    int deg   = g_cnt[d];

    float4 acc = make_float4(0.f, 0.f, 0.f, 0.f);
    float  den = 0.f;

    int sj_next = 0;
    if (lane < deg) sj_next = g_csrsrc[start + lane];

    for (int base = 0; base < deg; base += 32) {
        int m = min(32, deg - base);
        int sj = sj_next;
        int nb = base + 32;
        if (nb + lane < deg) sj_next = g_csrsrc[start + nb + lane];

        float w0 = 0.f, w1 = 0.f;
        if (lane < m) {
            float2 as = ((const float2*)g_asrc)[sj];
            w0 = __expf(lrelu(as.x + adp.x));
            w1 = __expf(lrelu(as.y + adp.y));
        }
        for (int k = 0; k < m; ++k) {
            int   s  = __shfl_sync(0xffffffffu, sj, k);
            float wa = __shfl_sync(0xffffffffu, w0, k);
            float wb = __shfl_sync(0xffffffffu, w1, k);
            float w  = (hsel == 0) ? wa : wb;
            float4 v = ((const float4*)(h + (size_t)s * FF))[lane];
            acc.x += w * v.x; acc.y += w * v.y;
            acc.z += w * v.z; acc.w += w * v.w;
            den += w;
        }
    }
    float inv = 1.0f / (den + 1e-16f);
    float4 b  = ((const float4*)bias)[lane];
    float4 o  = make_float4(acc.x * inv + b.x, acc.y * inv + b.y,
                            acc.z * inv + b.z, acc.w * inv + b.w);
    ((float4*)(out + (size_t)d * FF))[lane] = o;
}

// ---------------- layer-1 aggregation (mean over heads), needed dsts only ----
// warp per dst node; lane l handles cols {2l, 2l+1} of both heads
__global__ void agg_mean_csr(const float* __restrict__ h,
                             const float* __restrict__ bias,
                             float* __restrict__ out, int n) {
    int d    = (blockIdx.x * blockDim.x + threadIdx.x) >> 5;
    int lane = threadIdx.x & 31;
    if (d >= n) return;
    if (!g_need[d]) return;        // dead dst: scorer never reads it

    float2 adp = ((const float2*)g_adst)[d];
    int start = g_start[d];
    int deg   = g_cnt[d];
    int c = lane * 2;

    float2 acc0 = make_float2(0.f, 0.f), acc1 = make_float2(0.f, 0.f);
    float den0 = 0.f, den1 = 0.f;

    int sj_next = 0;
    if (lane < deg) sj_next = g_csrsrc[start + lane];

    for (int base = 0; base < deg; base += 32) {
        int m = min(32, deg - base);
        int sj = sj_next;
        int nb = base + 32;
        if (nb + lane < deg) sj_next = g_csrsrc[start + nb + lane];

        float w0 = 0.f, w1 = 0.f;
        if (lane < m) {
            float2 as = ((const float2*)g_asrc)[sj];
            w0 = __expf(lrelu(as.x + adp.x));
            w1 = __expf(lrelu(as.y + adp.y));
        }
        for (int k = 0; k < m; ++k) {
            int   s  = __shfl_sync(0xffffffffu, sj, k);
            float wa = __shfl_sync(0xffffffffu, w0, k);
            float wb = __shfl_sync(0xffffffffu, w1, k);
            const float* hr = h + (size_t)s * FF;
            float2 v0 = *(const float2*)(hr + c);
            float2 v1 = *(const float2*)(hr + CC + c);
            acc0.x += wa * v0.x; acc0.y += wa * v0.y;
            acc1.x += wb * v1.x; acc1.y += wb * v1.y;
            den0 += wa; den1 += wb;
        }
    }
    float i0 = 1.0f / (den0 + 1e-16f);
    float i1 = 1.0f / (den1 + 1e-16f);
    float2 b = ((const float2*)bias)[lane];
    float2 o = make_float2(0.5f * (acc0.x * i0 + acc1.x * i1) + b.x,
                           0.5f * (acc0.y * i0 + acc1.y * i1) + b.y);
    *(float2*)(out + (size_t)d * CC + c) = o;
}

// ---------------- final scorer ----------------
__global__ void score_pairs(const float* __restrict__ emb,
                            const int* __restrict__ uidx,
                            const int* __restrict__ iidx,
                            int nu, float* __restrict__ out, int B) {
    int warp = (blockIdx.x * blockDim.x + threadIdx.x) >> 5;
    int lane = threadIdx.x & 31;
    if (warp >= B) return;
    const float* gu = emb + (size_t)uidx[warp] * CC;
    const float* gi = emb + (size_t)(nu + iidx[warp]) * CC;
    float s = gu[lane] * gi[lane] + gu[lane + 32] * gi[lane + 32];
#pragma unroll
    for (int o = 16; o > 0; o >>= 1) s += __shfl_down_sync(0xffffffffu, s, o);
    if (lane == 0) out[warp] = s;
}

// ---------------- launch ----------------
extern "C" void kernel_launch(void* const* d_in, const int* in_sizes, int n_in,
                              void* d_out, int out_size) {
    const float* Gu  = (const float*)d_in[0];
    const float* Gi  = (const float*)d_in[1];
    const float* W0  = (const float*)d_in[2];
    const float* as0 = (const float*)d_in[3];
    const float* ad0 = (const float*)d_in[4];
    const float* b0  = (const float*)d_in[5];
    const float* W1  = (const float*)d_in[6];
    const float* as1 = (const float*)d_in[7];
    const float* ad1 = (const float*)d_in[8];
    const float* b1  = (const float*)d_in[9];
    const int*   ei  = (const int*)d_in[10];
    const int*   uix = (const int*)d_in[11];
    const int*   iix = (const int*)d_in[12];
    float* out = (float*)d_out;

    const int NU = in_sizes[0] / D0;
    const int NI = in_sizes[1] / D0;
    const int N  = NU + NI;
    const int E  = in_sizes[10] / 2;
    const int B  = in_sizes[11];
    const int* src = ei;
    const int* dst = ei + E;

    float *ph, *px1, *pout1;
    cudaGetSymbolAddress((void**)&ph,    g_h);
    cudaGetSymbolAddress((void**)&px1,   g_x1);
    cudaGetSymbolAddress((void**)&pout1, g_out1);

    const int TB = 256;
    int gemm_blocks  = (N + 15) / 16;
    int attn_grid    = (N * HH * 32 + TB - 1) / TB;
    int edge_grid    = (E + TB - 1) / TB;
    int node_grid    = (N + TB - 1) / TB;
    int warpnode_grid= (N * 32 + TB - 1) / TB;
    int scan_blocks  = (N + SCAN_BLK - 1) / SCAN_BLK;

    // ---------- CSR build (shared by both layers) ----------
    zero_cnt_need<<<node_grid, TB>>>(N);
    hist_dst<<<edge_grid, TB>>>(dst, E);
    mark_needed<<<(2 * B + TB - 1) / TB, TB>>>(uix, iix, NU, B);
    scan1<<<scan_blocks, SCAN_BLK>>>(N);
    scan2<<<1, 256>>>(scan_blocks);
    scan3<<<scan_blocks, SCAN_BLK>>>(N);
    scatter_edges<<<edge_grid, TB>>>(src, dst, E);

    // ---------- layer 0 ----------
    gemm_rowpanel<D0><<<gemm_blocks, 256>>>(Gu, Gi, NU, W0, ph, N);
    attn_scores<<<attn_grid, TB>>>(ph, as0, ad0, N);
    agg_concat_csr<<<warpnode_grid, TB>>>(ph, b0, px1, N);

    // ---------- layer 1 ----------
    gemm_rowpanel<FF><<<gemm_blocks, 256>>>(px1, px1, N, W1, ph, N);
    attn_scores<<<attn_grid, TB>>>(ph, as1, ad1, N);
    agg_mean_csr<<<warpnode_grid, TB>>>(ph, b1, pout1, N);

    // ---------- scorer ----------
    score_pairs<<<(B * 32 + TB - 1) / TB, TB>>>(pout1, uix, iix, NU, out, B);
}

// round 11
// speedup vs baseline: 1.5926x; 1.1822x over previous
#include <cuda_runtime.h>
#include <math.h>
#include <math_constants.h>

// Problem constants (fixed by setup_inputs)
#define D0   64
#define HH   2
#define CC   64
#define FF   128
#define NMAX 80000
#define EMAX 1280000
#define SCAN_BLK 1024

// ---------------- scratch ----------------
__device__ float g_z   [(size_t)NMAX * 256];  // z0: N x 128 (2h x 64), z1: N x 256 (2h x 128)
__device__ float g_x1  [(size_t)NMAX * FF];   // layer-0 output
__device__ float g_out1[(size_t)NMAX * CC];   // layer-1 output (needed rows only)
__device__ float g_asrc[NMAX * HH];
__device__ float g_adst[NMAX * HH];
__device__ float g_den [NMAX * HH];
__device__ float g_v0  [256];                 // [src/dst][h][64]
__device__ float g_v1  [512];                 // [src/dst][h][128]
__device__ int   g_cnt   [NMAX];
__device__ int   g_start [NMAX];
__device__ int   g_cursor[NMAX];
__device__ int   g_need  [NMAX];
__device__ int   g_part  [256];
__device__ int   g_csrsrc[EMAX];
__device__ int   g_nlist [NMAX];
__device__ int   g_ncnt;

__device__ __forceinline__ float lrelu(float x) {
    return x >= 0.0f ? x : 0.2f * x;
}

// ---------------- CSR build ----------------
__global__ void zero_cnt_need(int n) {
    int i = blockIdx.x * blockDim.x + threadIdx.x;
    if (i < n) { g_cnt[i] = 0; g_need[i] = 0; }
    if (i == 0) g_ncnt = 0;
}

__global__ void hist_dst(const int* __restrict__ dst, int E) {
    int e = blockIdx.x * blockDim.x + threadIdx.x;
    if (e < E) atomicAdd(&g_cnt[dst[e]], 1);
}

__global__ void mark_needed(const int* __restrict__ uidx,
                            const int* __restrict__ iidx,
                            int nu, int B) {
    int i = blockIdx.x * blockDim.x + threadIdx.x;
    if (i < B)          g_need[uidx[i]] = 1;
    else if (i < 2 * B) g_need[nu + iidx[i - B]] = 1;
}

__global__ void build_nlist(int n) {
    int i = blockIdx.x * blockDim.x + threadIdx.x;
    if (i < n && g_need[i]) {
        int pos = atomicAdd(&g_ncnt, 1);
        g_nlist[pos] = i;
    }
}

__global__ void scan1(int n) {
    __shared__ int sm[SCAN_BLK];
    int i = blockIdx.x * SCAN_BLK + threadIdx.x;
    int v = (i < n) ? g_cnt[i] : 0;
    sm[threadIdx.x] = v;
    __syncthreads();
    for (int off = 1; off < SCAN_BLK; off <<= 1) {
        int t = (threadIdx.x >= off) ? sm[threadIdx.x - off] : 0;
        __syncthreads();
        sm[threadIdx.x] += t;
        __syncthreads();
    }
    if (i < n) g_start[i] = sm[threadIdx.x] - v;
    if (threadIdx.x == SCAN_BLK - 1) g_part[blockIdx.x] = sm[SCAN_BLK - 1];
}

__global__ void scan2(int nblocks) {
    __shared__ int sm[256];
    int t = threadIdx.x;
    int v = (t < nblocks) ? g_part[t] : 0;
    sm[t] = v;
    __syncthreads();
    for (int off = 1; off < 256; off <<= 1) {
        int u = (t >= off) ? sm[t - off] : 0;
        __syncthreads();
        sm[t] += u;
        __syncthreads();
    }
    if (t < nblocks) g_part[t] = sm[t] - v;
}

__global__ void scan3(int n) {
    int i = blockIdx.x * SCAN_BLK + threadIdx.x;
    if (i >= n) return;
    int s = g_start[i] + g_part[blockIdx.x];
    g_start[i]  = s;
    g_cursor[i] = s;
}

__global__ void scatter_edges(const int* __restrict__ src,
                              const int* __restrict__ dst, int E) {
    int e = blockIdx.x * blockDim.x + threadIdx.x;
    if (e >= E) return;
    int pos = atomicAdd(&g_cursor[dst[e]], 1);
    g_csrsrc[pos] = src[e];
}

// ---------------- attention projection vectors ----------------
// v0[sel][h][k] = sum_c W0[k][h*64+c] * att[h][c], k in [0,64)
__global__ void precompute_v0(const float* __restrict__ W0,
                              const float* __restrict__ as0,
                              const float* __restrict__ ad0) {
    int t = threadIdx.x;               // 0..255
    int sel = t >> 7, rem = t & 127, h = rem >> 6, k = rem & 63;
    const float* att = sel ? ad0 : as0;
    float s = 0.0f;
    for (int c = 0; c < 64; ++c)
        s += W0[k * FF + h * 64 + c] * att[h * 64 + c];
    g_v0[t] = s;
}

// v1[sel][h][k] = sum_c W1[k][h*64+c] * att[h][c], k in [0,128)
__global__ void precompute_v1(const float* __restrict__ W1,
                              const float* __restrict__ as1,
                              const float* __restrict__ ad1) {
    int gid = blockIdx.x * blockDim.x + threadIdx.x;   // 0..511
    int sel = gid >> 8, rem = gid & 255, h = rem >> 7, k = rem & 127;
    const float* att = sel ? ad1 : as1;
    float s = 0.0f;
    for (int c = 0; c < 64; ++c)
        s += W1[k * FF + h * 64 + c] * att[h * 64 + c];
    g_v1[gid] = s;
}

// ---------------- layer-0 scores from raw x ----------------
__global__ void attn0_scores(const float* __restrict__ Gu,
                             const float* __restrict__ Gi,
                             int nu, int n) {
    int gw   = (blockIdx.x * blockDim.x + threadIdx.x) >> 5;
    int lane = threadIdx.x & 31;
    if (gw >= n) return;
    const float* xr = (gw < nu) ? Gu + (size_t)gw * D0
                                : Gi + (size_t)(gw - nu) * D0;
    float2 xv  = ((const float2*)xr)[lane];
    float2 vs0 = ((const float2*)(g_v0      ))[lane];
    float2 vs1 = ((const float2*)(g_v0 +  64))[lane];
    float2 vd0 = ((const float2*)(g_v0 + 128))[lane];
    float2 vd1 = ((const float2*)(g_v0 + 192))[lane];
    float s0 = xv.x * vs0.x + xv.y * vs0.y;
    float s1 = xv.x * vs1.x + xv.y * vs1.y;
    float d0 = xv.x * vd0.x + xv.y * vd0.y;
    float d1 = xv.x * vd1.x + xv.y * vd1.y;
#pragma unroll
    for (int o = 16; o > 0; o >>= 1) {
        s0 += __shfl_down_sync(0xffffffffu, s0, o);
        s1 += __shfl_down_sync(0xffffffffu, s1, o);
        d0 += __shfl_down_sync(0xffffffffu, d0, o);
        d1 += __shfl_down_sync(0xffffffffu, d1, o);
    }
    if (lane == 0) {
        g_asrc[gw * 2] = s0; g_asrc[gw * 2 + 1] = s1;
        g_adst[gw * 2] = d0; g_adst[gw * 2 + 1] = d1;
    }
}

// ---------------- layer-1 scores from x1 ----------------
__global__ void attn1_scores(const float* __restrict__ x1, int n) {
    int gw   = (blockIdx.x * blockDim.x + threadIdx.x) >> 5;
    int lane = threadIdx.x & 31;
    if (gw >= n) return;
    float4 xv  = ((const float4*)(x1 + (size_t)gw * FF))[lane];
    float4 vs0 = ((const float4*)(g_v1      ))[lane];
    float4 vs1 = ((const float4*)(g_v1 + 128))[lane];
    float4 vd0 = ((const float4*)(g_v1 + 256))[lane];
    float4 vd1 = ((const float4*)(g_v1 + 384))[lane];
    float s0 = xv.x*vs0.x + xv.y*vs0.y + xv.z*vs0.z + xv.w*vs0.w;
    float s1 = xv.x*vs1.x + xv.y*vs1.y + xv.z*vs1.z + xv.w*vs1.w;
    float d0 = xv.x*vd0.x + xv.y*vd0.y + xv.z*vd0.z + xv.w*vd0.w;
    float d1 = xv.x*vd1.x + xv.y*vd1.y + xv.z*vd1.z + xv.w*vd1.w;
#pragma unroll
    for (int o = 16; o > 0; o >>= 1) {
        s0 += __shfl_down_sync(0xffffffffu, s0, o);
        s1 += __shfl_down_sync(0xffffffffu, s1, o);
        d0 += __shfl_down_sync(0xffffffffu, d0, o);
        d1 += __shfl_down_sync(0xffffffffu, d1, o);
    }
    if (lane == 0) {
        g_asrc[gw * 2] = s0; g_asrc[gw * 2 + 1] = s1;
        g_adst[gw * 2] = d0; g_adst[gw * 2 + 1] = d1;
    }
}

// ---------------- layer-0 aggregation: z_h[d] = sum_e w_h * x[s] (x is 64-dim) --
__global__ void agg0(const float* __restrict__ Gu,
                     const float* __restrict__ Gi,
                     int nu, int n) {
    int d    = (blockIdx.x * blockDim.x + threadIdx.x) >> 5;
    int lane = threadIdx.x & 31;
    if (d >= n) return;

    float2 adp = ((const float2*)g_adst)[d];
    int start = g_start[d];
    int deg   = g_cnt[d];

    float2 a0 = make_float2(0.f, 0.f), a1 = make_float2(0.f, 0.f);
    float den0 = 0.f, den1 = 0.f;

    int sj_next = 0;
    if (lane < deg) sj_next = g_csrsrc[start + lane];

    for (int base = 0; base < deg; base += 32) {
        int m = min(32, deg - base);
        int sj = sj_next;
        int nb = base + 32;
        if (nb + lane < deg) sj_next = g_csrsrc[start + nb + lane];

        float w0 = 0.f, w1 = 0.f;
        if (lane < m) {
            float2 as = ((const float2*)g_asrc)[sj];
            w0 = __expf(lrelu(as.x + adp.x));
            w1 = __expf(lrelu(as.y + adp.y));
        }
        for (int k = 0; k < m; ++k) {
            int   s  = __shfl_sync(0xffffffffu, sj, k);
            float wa = __shfl_sync(0xffffffffu, w0, k);
            float wb = __shfl_sync(0xffffffffu, w1, k);
            const float* xr = (s < nu) ? Gu + (size_t)s * D0
                                       : Gi + (size_t)(s - nu) * D0;
            float2 v = ((const float2*)xr)[lane];
            a0.x += wa * v.x; a0.y += wa * v.y;
            a1.x += wb * v.x; a1.y += wb * v.y;
            den0 += wa; den1 += wb;
        }
    }
    float* z = g_z + (size_t)d * 128;
    ((float2*)z)[lane]        = a0;   // head0 cols [2l, 2l+1]
    ((float2*)(z + 64))[lane] = a1;   // head1
    if (lane == 0) { g_den[d * 2] = den0; g_den[d * 2 + 1] = den1; }
}

// ---------------- layer-0 projection: x1[d] = concat_h((z_h/den_h) @ W0_h) + b0 --
__global__ void transform0(const float* __restrict__ W0,
                           const float* __restrict__ b0, int n) {
    __shared__ float zs[32][128];
    __shared__ float invs[32][2];
    int r0 = blockIdx.x * 32;
    int t  = threadIdx.x;

    for (int idx = t; idx < 32 * 128; idx += 256) {
        int r = idx >> 7, c = idx & 127;
        int gr = r0 + r;
        zs[r][c] = (gr < n) ? g_z[(size_t)gr * 128 + c] : 0.f;
    }
    if (t < 64) {
        int r = t >> 1, hh = t & 1;
        int gr = r0 + r;
        float den = (gr < n) ? g_den[gr * 2 + hh] : 1.f;
        invs[r][hh] = 1.0f / (den + 1e-16f);
    }
    __syncthreads();

    int col = t & 127, half = t >> 7, h = col >> 6;
    int rbase = half * 16;
    float acc[16];
#pragma unroll
    for (int r = 0; r < 16; ++r) acc[r] = 0.f;

    for (int k = 0; k < 64; ++k) {
        float w = W0[k * FF + col];
#pragma unroll
        for (int r = 0; r < 16; ++r) acc[r] += zs[rbase + r][h * 64 + k] * w;
    }
    float bb = b0[col];
#pragma unroll
    for (int r = 0; r < 16; ++r) {
        int gr = r0 + rbase + r;
        if (gr < n)
            g_x1[(size_t)gr * FF + col] = acc[r] * invs[rbase + r][h] + bb;
    }
}

// ---------------- layer-1 aggregation (needed dsts): z_h[d] = sum w_h*x1[s] ----
__global__ void agg1(int n) {
    int d    = (blockIdx.x * blockDim.x + threadIdx.x) >> 5;
    int lane = threadIdx.x & 31;
    if (d >= n) return;
    if (!g_need[d]) return;

    float2 adp = ((const float2*)g_adst)[d];
    int start = g_start[d];
    int deg   = g_cnt[d];

    float4 a0 = make_float4(0.f,0.f,0.f,0.f), a1 = make_float4(0.f,0.f,0.f,0.f);
    float den0 = 0.f, den1 = 0.f;

    int sj_next = 0;
    if (lane < deg) sj_next = g_csrsrc[start + lane];

    for (int base = 0; base < deg; base += 32) {
        int m = min(32, deg - base);
        int sj = sj_next;
        int nb = base + 32;
        if (nb + lane < deg) sj_next = g_csrsrc[start + nb + lane];

        float w0 = 0.f, w1 = 0.f;
        if (lane < m) {
            float2 as = ((const float2*)g_asrc)[sj];
            w0 = __expf(lrelu(as.x + adp.x));
            w1 = __expf(lrelu(as.y + adp.y));
        }
        for (int k = 0; k < m; ++k) {
            int   s  = __shfl_sync(0xffffffffu, sj, k);
            float wa = __shfl_sync(0xffffffffu, w0, k);
            float wb = __shfl_sync(0xffffffffu, w1, k);
            float4 v = ((const float4*)(g_x1 + (size_t)s * FF))[lane];
            a0.x += wa * v.x; a0.y += wa * v.y; a0.z += wa * v.z; a0.w += wa * v.w;
            a1.x += wb * v.x; a1.y += wb * v.y; a1.z += wb * v.z; a1.w += wb * v.w;
            den0 += wa; den1 += wb;
        }
    }
    float* z = g_z + (size_t)d * 256;
    ((float4*)z)[lane]         = a0;   // head0 cols [4l..4l+3]
    ((float4*)(z + 128))[lane] = a1;   // head1
    if (lane == 0) { g_den[d * 2] = den0; g_den[d * 2 + 1] = den1; }
}

// ---------------- layer-1 projection on compacted needed rows -----------------
__global__ void transform1(const float* __restrict__ W1,
                           const float* __restrict__ b1) {
    __shared__ float zs[16][256];
    __shared__ float invs[16][2];
    __shared__ int   rid[16];
    int cnt = g_ncnt;
    int r0 = blockIdx.x * 16;
    if (r0 >= cnt) return;
    int t = threadIdx.x;

    if (t < 16) {
        int gr = r0 + t;
        rid[t] = (gr < cnt) ? g_nlist[gr] : -1;
    }
    __syncthreads();
    for (int idx = t; idx < 16 * 256; idx += 256) {
        int r = idx >> 8, c = idx & 255;
        int id = rid[r];
        zs[r][c] = (id >= 0) ? g_z[(size_t)id * 256 + c] : 0.f;
    }
    if (t < 32) {
        int r = t >> 1, hh = t & 1;
        int id = rid[r];
        float den = (id >= 0) ? g_den[id * 2 + hh] : 1.f;
        invs[r][hh] = 1.0f / (den + 1e-16f);
    }
    __syncthreads();

    int col = t & 63, q = t >> 6;      // q in 0..3, 4 rows each
    int rbase = q * 4;
    float acc0[4], acc1[4];
#pragma unroll
    for (int r = 0; r < 4; ++r) { acc0[r] = 0.f; acc1[r] = 0.f; }

    for (int k = 0; k < 128; ++k) {
        float w0c = W1[k * FF + col];        // head0 output block
        float w1c = W1[k * FF + 64 + col];   // head1 output block
#pragma unroll
        for (int r = 0; r < 4; ++r) {
            acc0[r] += zs[rbase + r][k]       * w0c;
            acc1[r] += zs[rbase + r][128 + k] * w1c;
        }
    }
    float bb = b1[col];
#pragma unroll
    for (int r = 0; r < 4; ++r) {
        int id = rid[rbase + r];
        if (id >= 0)
            g_out1[(size_t)id * CC + col] =
                0.5f * (acc0[r] * invs[rbase + r][0] + acc1[r] * invs[rbase + r][1]) + bb;
    }
}

// ---------------- final scorer ----------------
__global__ void score_pairs(const float* __restrict__ emb,
                            const int* __restrict__ uidx,
                            const int* __restrict__ iidx,
                            int nu, float* __restrict__ out, int B) {
    int warp = (blockIdx.x * blockDim.x + threadIdx.x) >> 5;
    int lane = threadIdx.x & 31;
    if (warp >= B) return;
    const float* gu = emb + (size_t)uidx[warp] * CC;
    const float* gi = emb + (size_t)(nu + iidx[warp]) * CC;
    float s = gu[lane] * gi[lane] + gu[lane + 32] * gi[lane + 32];
#pragma unroll
    for (int o = 16; o > 0; o >>= 1) s += __shfl_down_sync(0xffffffffu, s, o);
    if (lane == 0) out[warp] = s;
}

// ---------------- launch ----------------
extern "C" void kernel_launch(void* const* d_in, const int* in_sizes, int n_in,
                              void* d_out, int out_size) {
    const float* Gu  = (const float*)d_in[0];
    const float* Gi  = (const float*)d_in[1];
    const float* W0  = (const float*)d_in[2];
    const float* as0 = (const float*)d_in[3];
    const float* ad0 = (const float*)d_in[4];
    const float* b0  = (const float*)d_in[5];
    const float* W1  = (const float*)d_in[6];
    const float* as1 = (const float*)d_in[7];
    const float* ad1 = (const float*)d_in[8];
    const float* b1  = (const float*)d_in[9];
    const int*   ei  = (const int*)d_in[10];
    const int*   uix = (const int*)d_in[11];
    const int*   iix = (const int*)d_in[12];
    float* out = (float*)d_out;

    const int NU = in_sizes[0] / D0;
    const int NI = in_sizes[1] / D0;
    const int N  = NU + NI;
    const int E  = in_sizes[10] / 2;
    const int B  = in_sizes[11];
    const int* src = ei;
    const int* dst = ei + E;

    float *px1, *pout1;
    cudaGetSymbolAddress((void**)&px1,   g_x1);
    cudaGetSymbolAddress((void**)&pout1, g_out1);

    const int TB = 256;
    int edge_grid    = (E + TB - 1) / TB;
    int node_grid    = (N + TB - 1) / TB;
    int warpnode_grid= (N * 32 + TB - 1) / TB;
    int scan_blocks  = (N + SCAN_BLK - 1) / SCAN_BLK;

    // ---------- CSR build + projection vectors ----------
    zero_cnt_need<<<node_grid, TB>>>(N);
    precompute_v0<<<1, 256>>>(W0, as0, ad0);
    precompute_v1<<<2, 256>>>(W1, as1, ad1);
    hist_dst<<<edge_grid, TB>>>(dst, E);
    mark_needed<<<(2 * B + TB - 1) / TB, TB>>>(uix, iix, NU, B);
    build_nlist<<<node_grid, TB>>>(N);
    scan1<<<scan_blocks, SCAN_BLK>>>(N);
    scan2<<<1, 256>>>(scan_blocks);
    scan3<<<scan_blocks, SCAN_BLK>>>(N);
    scatter_edges<<<edge_grid, TB>>>(src, dst, E);

    // ---------- layer 0 ----------
    attn0_scores<<<warpnode_grid, TB>>>(Gu, Gi, NU, N);
    agg0<<<warpnode_grid, TB>>>(Gu, Gi, NU, N);
    transform0<<<(N + 31) / 32, 256>>>(W0, b0, N);

    // ---------- layer 1 ----------
    attn1_scores<<<warpnode_grid, TB>>>(px1, N);
    agg1<<<warpnode_grid, TB>>>(N);
    transform1<<<(2 * 8192 + 15) / 16, 256>>>(W1, b1);

    // ---------- scorer ----------
    score_pairs<<<(B * 32 + TB - 1) / TB, TB>>>(pout1, uix, iix, NU, out, B);
}

// round 13
// speedup vs baseline: 1.7908x; 1.1244x over previous
#include <cuda_runtime.h>
#include <math.h>
#include <math_constants.h>

// Problem constants (fixed by setup_inputs)
#define D0   64
#define HH   2
#define CC   64
#define FF   128
#define NMAX 80000
#define EMAX 1280000
#define SCAN_BLK 1024

// ---------------- scratch ----------------
__device__ float g_z   [(size_t)NMAX * 256];
__device__ float g_x1  [(size_t)NMAX * FF];
__device__ float g_out1[(size_t)NMAX * CC];
__device__ float g_asrc[NMAX * HH];
__device__ float g_adst[NMAX * HH];
__device__ float g_den [NMAX * HH];
__device__ float g_v0  [256];                 // [src/dst][h][64]
__device__ float g_v1  [512];                 // [src/dst][h][128]
__device__ int   g_cnt   [NMAX];
__device__ int   g_start [NMAX];
__device__ int   g_cursor[NMAX];
__device__ int   g_need  [NMAX];
__device__ int   g_part  [256];
__device__ int   g_csrsrc[EMAX];
__device__ int   g_nlist [NMAX];
__device__ int   g_ncnt;

__device__ __forceinline__ float lrelu(float x) {
    return x >= 0.0f ? x : 0.2f * x;
}

// ---------------- fused setup: zero counters + projection vectors ----------------
__global__ void setup(const float* __restrict__ W0,
                      const float* __restrict__ as0,
                      const float* __restrict__ ad0,
                      const float* __restrict__ W1,
                      const float* __restrict__ as1,
                      const float* __restrict__ ad1,
                      int n) {
    int b = blockIdx.x;
    int t = threadIdx.x;
    if (b == 0) {
        // v0[sel][h][k], k in [0,64)
        int sel = t >> 7, rem = t & 127, h = rem >> 6, k = rem & 63;
        const float* att = sel ? ad0 : as0;
        float s = 0.0f;
        for (int c = 0; c < 64; ++c)
            s += W0[k * FF + h * 64 + c] * att[h * 64 + c];
        g_v0[t] = s;
        if (t == 0) g_ncnt = 0;
    } else if (b <= 2) {
        // v1[sel][h][k], k in [0,128)
        int gid = (b - 1) * 256 + t;
        int sel = gid >> 8, rem = gid & 255, h = rem >> 7, k = rem & 127;
        const float* att = sel ? ad1 : as1;
        float s = 0.0f;
        for (int c = 0; c < 64; ++c)
            s += W1[k * FF + h * 64 + c] * att[h * 64 + c];
        g_v1[gid] = s;
    } else {
        int i = (b - 3) * 256 + t;
        if (i < n) { g_cnt[i] = 0; g_need[i] = 0; }
    }
}

// ---------------- histogram: 4 edges per thread ----------------
__global__ void hist_dst(const int* __restrict__ dst, int E) {
    int base = (blockIdx.x * blockDim.x + threadIdx.x) * 4;
    int e1 = min(base + 4, E);
    for (int e = base; e < e1; ++e) atomicAdd(&g_cnt[dst[e]], 1);
}

// ---------------- fused mark + compact list (order-independent) ----------------
__global__ void mark_build(const int* __restrict__ uidx,
                           const int* __restrict__ iidx,
                           int nu, int B) {
    int i = blockIdx.x * blockDim.x + threadIdx.x;
    int node = -1;
    if (i < B)          node = uidx[i];
    else if (i < 2 * B) node = nu + iidx[i - B];
    if (node >= 0) {
        int old = atomicExch(&g_need[node], 1);
        if (!old) {
            int pos = atomicAdd(&g_ncnt, 1);
            g_nlist[pos] = node;
        }
    }
}

__global__ void scan1(int n) {
    __shared__ int sm[SCAN_BLK];
    int i = blockIdx.x * SCAN_BLK + threadIdx.x;
    int v = (i < n) ? g_cnt[i] : 0;
    sm[threadIdx.x] = v;
    __syncthreads();
    for (int off = 1; off < SCAN_BLK; off <<= 1) {
        int t = (threadIdx.x >= off) ? sm[threadIdx.x - off] : 0;
        __syncthreads();
        sm[threadIdx.x] += t;
        __syncthreads();
    }
    if (i < n) g_start[i] = sm[threadIdx.x] - v;
    if (threadIdx.x == SCAN_BLK - 1) g_part[blockIdx.x] = sm[SCAN_BLK - 1];
}

__global__ void scan2(int nblocks) {
    __shared__ int sm[256];
    int t = threadIdx.x;
    int v = (t < nblocks) ? g_part[t] : 0;
    sm[t] = v;
    __syncthreads();
    for (int off = 1; off < 256; off <<= 1) {
        int u = (t >= off) ? sm[t - off] : 0;
        __syncthreads();
        sm[t] += u;
        __syncthreads();
    }
    if (t < nblocks) g_part[t] = sm[t] - v;
}

__global__ void scan3(int n) {
    int i = blockIdx.x * SCAN_BLK + threadIdx.x;
    if (i >= n) return;
    int s = g_start[i] + g_part[blockIdx.x];
    g_start[i]  = s;
    g_cursor[i] = s;
}

__global__ void scatter_edges(const int* __restrict__ src,
                              const int* __restrict__ dst, int E) {
    int e = blockIdx.x * blockDim.x + threadIdx.x;
    if (e >= E) return;
    int pos = atomicAdd(&g_cursor[dst[e]], 1);
    g_csrsrc[pos] = src[e];
}

// ---------------- layer-0 scores from raw x ----------------
__global__ void attn0_scores(const float* __restrict__ Gu,
                             const float* __restrict__ Gi,
                             int nu, int n) {
    int gw   = (blockIdx.x * blockDim.x + threadIdx.x) >> 5;
    int lane = threadIdx.x & 31;
    if (gw >= n) return;
    const float* xr = (gw < nu) ? Gu + (size_t)gw * D0
                                : Gi + (size_t)(gw - nu) * D0;
    float2 xv  = ((const float2*)xr)[lane];
    float2 vs0 = ((const float2*)(g_v0      ))[lane];
    float2 vs1 = ((const float2*)(g_v0 +  64))[lane];
    float2 vd0 = ((const float2*)(g_v0 + 128))[lane];
    float2 vd1 = ((const float2*)(g_v0 + 192))[lane];
    float s0 = xv.x * vs0.x + xv.y * vs0.y;
    float s1 = xv.x * vs1.x + xv.y * vs1.y;
    float d0 = xv.x * vd0.x + xv.y * vd0.y;
    float d1 = xv.x * vd1.x + xv.y * vd1.y;
#pragma unroll
    for (int o = 16; o > 0; o >>= 1) {
        s0 += __shfl_down_sync(0xffffffffu, s0, o);
        s1 += __shfl_down_sync(0xffffffffu, s1, o);
        d0 += __shfl_down_sync(0xffffffffu, d0, o);
        d1 += __shfl_down_sync(0xffffffffu, d1, o);
    }
    if (lane == 0) {
        g_asrc[gw * 2] = s0; g_asrc[gw * 2 + 1] = s1;
        g_adst[gw * 2] = d0; g_adst[gw * 2 + 1] = d1;
    }
}

// ---------------- layer-0 aggregation: z_h[d] = sum_e w_h * x[s] ----------------
__global__ void agg0(const float* __restrict__ Gu,
                     const float* __restrict__ Gi,
                     int nu, int n) {
    int d    = (blockIdx.x * blockDim.x + threadIdx.x) >> 5;
    int lane = threadIdx.x & 31;
    if (d >= n) return;

    float2 adp = ((const float2*)g_adst)[d];
    int start = g_start[d];
    int deg   = g_cnt[d];

    float2 a0 = make_float2(0.f, 0.f), a1 = make_float2(0.f, 0.f);
    float den0 = 0.f, den1 = 0.f;

    int sj_next = 0;
    if (lane < deg) sj_next = g_csrsrc[start + lane];

    for (int base = 0; base < deg; base += 32) {
        int m = min(32, deg - base);
        int sj = sj_next;
        int nb = base + 32;
        if (nb + lane < deg) sj_next = g_csrsrc[start + nb + lane];

        float w0 = 0.f, w1 = 0.f;
        if (lane < m) {
            float2 as = ((const float2*)g_asrc)[sj];
            w0 = __expf(lrelu(as.x + adp.x));
            w1 = __expf(lrelu(as.y + adp.y));
        }
        for (int k = 0; k < m; ++k) {
            int   s  = __shfl_sync(0xffffffffu, sj, k);
            float wa = __shfl_sync(0xffffffffu, w0, k);
            float wb = __shfl_sync(0xffffffffu, w1, k);
            const float* xr = (s < nu) ? Gu + (size_t)s * D0
                                       : Gi + (size_t)(s - nu) * D0;
            float2 v = ((const float2*)xr)[lane];
            a0.x += wa * v.x; a0.y += wa * v.y;
            a1.x += wb * v.x; a1.y += wb * v.y;
            den0 += wa; den1 += wb;
        }
    }
    float* z = g_z + (size_t)d * 128;
    ((float2*)z)[lane]        = a0;
    ((float2*)(z + 64))[lane] = a1;
    if (lane == 0) { g_den[d * 2] = den0; g_den[d * 2 + 1] = den1; }
}

// ---------------- layer-0 projection + fused layer-1 scores --------------------
__global__ void transform0(const float* __restrict__ W0,
                           const float* __restrict__ b0, int n) {
    __shared__ float zs[32][128];
    __shared__ float invs[32][2];
    int r0 = blockIdx.x * 32;
    int t  = threadIdx.x;

    for (int idx = t; idx < 32 * 128; idx += 256) {
        int r = idx >> 7, c = idx & 127;
        int gr = r0 + r;
        zs[r][c] = (gr < n) ? g_z[(size_t)gr * 128 + c] : 0.f;
    }
    if (t < 64) {
        int r = t >> 1, hh = t & 1;
        int gr = r0 + r;
        float den = (gr < n) ? g_den[gr * 2 + hh] : 1.f;
        invs[r][hh] = 1.0f / (den + 1e-16f);
    }
    __syncthreads();

    int col = t & 127, half = t >> 7, h = col >> 6;
    int rbase = half * 16;
    float acc[16];
#pragma unroll
    for (int r = 0; r < 16; ++r) acc[r] = 0.f;

    for (int k = 0; k < 64; ++k) {
        float w = W0[k * FF + col];
#pragma unroll
        for (int r = 0; r < 16; ++r) acc[r] += zs[rbase + r][h * 64 + k] * w;
    }
    float bb = b0[col];

    // all reads of zs (z-values) done -> safe to overwrite with x1 values
    __syncthreads();
#pragma unroll
    for (int r = 0; r < 16; ++r) {
        int gr = r0 + rbase + r;
        float x1v = acc[r] * invs[rbase + r][h] + bb;
        zs[rbase + r][col] = x1v;
        if (gr < n) g_x1[(size_t)gr * FF + col] = x1v;
    }
    __syncthreads();

    // fused layer-1 attention scores: warp w handles rows w*4 .. w*4+3
    int wid  = t >> 5;
    int lane = t & 31;
    float4 vs0 = ((const float4*)(g_v1      ))[lane];
    float4 vs1 = ((const float4*)(g_v1 + 128))[lane];
    float4 vd0 = ((const float4*)(g_v1 + 256))[lane];
    float4 vd1 = ((const float4*)(g_v1 + 384))[lane];
#pragma unroll
    for (int rr = 0; rr < 4; ++rr) {
        int r  = wid * 4 + rr;
        int gr = r0 + r;
        float4 xv = ((const float4*)zs[r])[lane];
        float s0 = xv.x*vs0.x + xv.y*vs0.y + xv.z*vs0.z + xv.w*vs0.w;
        float s1 = xv.x*vs1.x + xv.y*vs1.y + xv.z*vs1.z + xv.w*vs1.w;
        float d0 = xv.x*vd0.x + xv.y*vd0.y + xv.z*vd0.z + xv.w*vd0.w;
        float d1 = xv.x*vd1.x + xv.y*vd1.y + xv.z*vd1.z + xv.w*vd1.w;
#pragma unroll
        for (int o = 16; o > 0; o >>= 1) {
            s0 += __shfl_down_sync(0xffffffffu, s0, o);
            s1 += __shfl_down_sync(0xffffffffu, s1, o);
            d0 += __shfl_down_sync(0xffffffffu, d0, o);
            d1 += __shfl_down_sync(0xffffffffu, d1, o);
        }
        if (lane == 0 && gr < n) {
            g_asrc[gr * 2] = s0; g_asrc[gr * 2 + 1] = s1;
            g_adst[gr * 2] = d0; g_adst[gr * 2 + 1] = d1;
        }
    }
}

// ---------------- layer-1 aggregation over compacted needed dsts ----------------
__global__ void agg1() {
    int idx  = (blockIdx.x * blockDim.x + threadIdx.x) >> 5;
    int lane = threadIdx.x & 31;
    if (idx >= g_ncnt) return;
    int d = g_nlist[idx];

    float2 adp = ((const float2*)g_adst)[d];
    int start = g_start[d];
    int deg   = g_cnt[d];

    float4 a0 = make_float4(0.f,0.f,0.f,0.f), a1 = make_float4(0.f,0.f,0.f,0.f);
    float den0 = 0.f, den1 = 0.f;

    int sj_next = 0;
    if (lane < deg) sj_next = g_csrsrc[start + lane];

    for (int base = 0; base < deg; base += 32) {
        int m = min(32, deg - base);
        int sj = sj_next;
        int nb = base + 32;
        if (nb + lane < deg) sj_next = g_csrsrc[start + nb + lane];

        float w0 = 0.f, w1 = 0.f;
        if (lane < m) {
            float2 as = ((const float2*)g_asrc)[sj];
            w0 = __expf(lrelu(as.x + adp.x));
            w1 = __expf(lrelu(as.y + adp.y));
        }
        for (int k = 0; k < m; ++k) {
            int   s  = __shfl_sync(0xffffffffu, sj, k);
            float wa = __shfl_sync(0xffffffffu, w0, k);
            float wb = __shfl_sync(0xffffffffu, w1, k);
            float4 v = ((const float4*)(g_x1 + (size_t)s * FF))[lane];
            a0.x += wa * v.x; a0.y += wa * v.y; a0.z += wa * v.z; a0.w += wa * v.w;
            a1.x += wb * v.x; a1.y += wb * v.y; a1.z += wb * v.z; a1.w += wb * v.w;
            den0 += wa; den1 += wb;
        }
    }
    float* z = g_z + (size_t)d * 256;
    ((float4*)z)[lane]         = a0;
    ((float4*)(z + 128))[lane] = a1;
    if (lane == 0) { g_den[d * 2] = den0; g_den[d * 2 + 1] = den1; }
}

// ---------------- layer-1 projection on compacted needed rows -----------------
__global__ void transform1(const float* __restrict__ W1,
                           const float* __restrict__ b1) {
    __shared__ float zs[16][256];
    __shared__ float invs[16][2];
    __shared__ int   rid[16];
    int cnt = g_ncnt;
    int r0 = blockIdx.x * 16;
    if (r0 >= cnt) return;
    int t = threadIdx.x;

    if (t < 16) {
        int gr = r0 + t;
        rid[t] = (gr < cnt) ? g_nlist[gr] : -1;
    }
    __syncthreads();
    for (int idx = t; idx < 16 * 256; idx += 256) {
        int r = idx >> 8, c = idx & 255;
        int id = rid[r];
        zs[r][c] = (id >= 0) ? g_z[(size_t)id * 256 + c] : 0.f;
    }
    if (t < 32) {
        int r = t >> 1, hh = t & 1;
        int id = rid[r];
        float den = (id >= 0) ? g_den[id * 2 + hh] : 1.f;
        invs[r][hh] = 1.0f / (den + 1e-16f);
    }
    __syncthreads();

    int col = t & 63, q = t >> 6;
    int rbase = q * 4;
    float acc0[4], acc1[4];
#pragma unroll
    for (int r = 0; r < 4; ++r) { acc0[r] = 0.f; acc1[r] = 0.f; }

    for (int k = 0; k < 128; ++k) {
        float w0c = W1[k * FF + col];
        float w1c = W1[k * FF + 64 + col];
#pragma unroll
        for (int r = 0; r < 4; ++r) {
            acc0[r] += zs[rbase + r][k]       * w0c;
            acc1[r] += zs[rbase + r][128 + k] * w1c;
        }
    }
    float bb = b1[col];
#pragma unroll
    for (int r = 0; r < 4; ++r) {
        int id = rid[rbase + r];
        if (id >= 0)
            g_out1[(size_t)id * CC + col] =
                0.5f * (acc0[r] * invs[rbase + r][0] + acc1[r] * invs[rbase + r][1]) + bb;
    }
}

// ---------------- final scorer ----------------
__global__ void score_pairs(const float* __restrict__ emb,
                            const int* __restrict__ uidx,
                            const int* __restrict__ iidx,
                            int nu, float* __restrict__ out, int B) {
    int warp = (blockIdx.x * blockDim.x + threadIdx.x) >> 5;
    int lane = threadIdx.x & 31;
    if (warp >= B) return;
    const float* gu = emb + (size_t)uidx[warp] * CC;
    const float* gi = emb + (size_t)(nu + iidx[warp]) * CC;
    float s = gu[lane] * gi[lane] + gu[lane + 32] * gi[lane + 32];
#pragma unroll
    for (int o = 16; o > 0; o >>= 1) s += __shfl_down_sync(0xffffffffu, s, o);
    if (lane == 0) out[warp] = s;
}

// ---------------- launch ----------------
extern "C" void kernel_launch(void* const* d_in, const int* in_sizes, int n_in,
                              void* d_out, int out_size) {
    const float* Gu  = (const float*)d_in[0];
    const float* Gi  = (const float*)d_in[1];
    const float* W0  = (const float*)d_in[2];
    const float* as0 = (const float*)d_in[3];
    const float* ad0 = (const float*)d_in[4];
    const float* b0  = (const float*)d_in[5];
    const float* W1  = (const float*)d_in[6];
    const float* as1 = (const float*)d_in[7];
    const float* ad1 = (const float*)d_in[8];
    const float* b1  = (const float*)d_in[9];
    const int*   ei  = (const int*)d_in[10];
    const int*   uix = (const int*)d_in[11];
    const int*   iix = (const int*)d_in[12];
    float* out = (float*)d_out;

    const int NU = in_sizes[0] / D0;
    const int NI = in_sizes[1] / D0;
    const int N  = NU + NI;
    const int E  = in_sizes[10] / 2;
    const int B  = in_sizes[11];
    const int* src = ei;
    const int* dst = ei + E;

    float* pout1;
    cudaGetSymbolAddress((void**)&pout1, g_out1);

    const int TB = 256;
    int edge_grid    = (E + TB - 1) / TB;
    int hist_grid    = ((E + 3) / 4 + TB - 1) / TB;
    int node_grid    = (N + TB - 1) / TB;
    int warpnode_grid= (N * 32 + TB - 1) / TB;
    int scan_blocks  = (N + SCAN_BLK - 1) / SCAN_BLK;

    // ---------- setup + CSR build ----------
    setup<<<node_grid + 3, TB>>>(W0, as0, ad0, W1, as1, ad1, N);
    hist_dst<<<hist_grid, TB>>>(dst, E);
    mark_build<<<(2 * B + TB - 1) / TB, TB>>>(uix, iix, NU, B);
    scan1<<<scan_blocks, SCAN_BLK>>>(N);
    scan2<<<1, 256>>>(scan_blocks);
    scan3<<<scan_blocks, SCAN_BLK>>>(N);
    scatter_edges<<<edge_grid, TB>>>(src, dst, E);

    // ---------- layer 0 (+ fused layer-1 scores) ----------
    attn0_scores<<<warpnode_grid, TB>>>(Gu, Gi, NU, N);
    agg0<<<warpnode_grid, TB>>>(Gu, Gi, NU, N);
    transform0<<<(N + 31) / 32, 256>>>(W0, b0, N);

    // ---------- layer 1 ----------
    agg1<<<(2 * B * 32 + TB - 1) / TB, TB>>>();
    transform1<<<(2 * 8192 + 15) / 16, 256>>>(W1, b1);

    // ---------- scorer ----------
    score_pairs<<<(B * 32 + TB - 1) / TB, TB>>>(pout1, uix, iix, NU, out, B);
}